// round 1
// baseline (speedup 1.0000x reference)
#include <cuda_runtime.h>
#include <math.h>

// Problem constants
#define N_TOK 16384
#define H_DIM 1024
#define E_NUM 8
#define E_DIM 512
#define VOCAB 50257
#define PADMAX (N_TOK + E_NUM * 128)   // 17408: worst-case padded grouped rows

// ---------------- routing state + scratch (static device memory) ------------
__device__ int d_counts[E_NUM];
__device__ int d_cursor[E_NUM];
__device__ int d_poff[E_NUM + 1];       // padded group offsets (multiples of 128)
__device__ int d_padded_total;
__device__ int d_perm[PADMAX];          // grouped-row -> token index (-1 = pad)

__device__ float g_GUs[(size_t)N_TOK * 2048];   // shared gate|up pre-activation
__device__ float g_Hs [(size_t)N_TOK * 1024];   // shared swiglu hidden
__device__ float g_GUr[(size_t)PADMAX * 1024];  // routed gate|up pre-activation
__device__ float g_Hr [(size_t)PADMAX * 512];   // routed swiglu hidden

// ---------------- routing kernels -------------------------------------------
__global__ void k_init() {
    int i = blockIdx.x * blockDim.x + threadIdx.x;
    if (i < E_NUM) { d_counts[i] = 0; d_cursor[i] = 0; }
    for (int j = i; j < PADMAX; j += gridDim.x * blockDim.x) d_perm[j] = -1;
}

__device__ __forceinline__ int expert_of(int t) {
    t = t < 0 ? 0 : (t > VOCAB - 1 ? VOCAB - 1 : t);
    return t & (E_NUM - 1);
}

__global__ void k_hist(const int* __restrict__ tok) {
    int i = blockIdx.x * blockDim.x + threadIdx.x;
    if (i < N_TOK) atomicAdd(&d_counts[expert_of(tok[i])], 1);
}

__global__ void k_scan() {
    if (threadIdx.x == 0 && blockIdx.x == 0) {
        int acc = 0;
        d_poff[0] = 0;
        for (int e = 0; e < E_NUM; e++) {
            int p = (d_counts[e] + 127) & ~127;   // pad each group to 128
            acc += p;
            d_poff[e + 1] = acc;
        }
        d_padded_total = acc;
    }
}

__global__ void k_scatter(const int* __restrict__ tok) {
    int i = blockIdx.x * blockDim.x + threadIdx.x;
    if (i < N_TOK) {
        int e = expert_of(tok[i]);
        int p = atomicAdd(&d_cursor[e], 1);
        d_perm[d_poff[e] + p] = i;
    }
}

// ---------------- generic tiled SGEMM ---------------------------------------
#define BM 128
#define BN 128
#define BK 16

#define F_GATHER  1   // A row index = d_perm[global row] (-1 -> zero row)
#define F_SCATTER 2   // C row index = d_perm[global row] (-1 -> skip)
#define F_ACCUM   4   // C += acc  (else C = acc)
#define F_EXPERT  8   // B += expert(row0) * ew_stride
#define F_LIMIT  16   // blocks with row0 >= d_padded_total exit

__global__ __launch_bounds__(256, 2)
void k_sgemm(const float* __restrict__ A,
             const float* __restrict__ B0,
             const float* __restrict__ B1,
             float* __restrict__ C,
             int K, int split, int ldb, int ldc,
             long long ew_stride, int flags)
{
    __shared__ float As[BK][BM];
    __shared__ float Bs[BK][BN];
    __shared__ int   s_map[BM];

    int row0 = blockIdx.y * BM;
    if ((flags & F_LIMIT) && row0 >= d_padded_total) return;
    int col0 = blockIdx.x * BN;

    // select B operand half (gate vs up), then expert offset
    const float* Bsel;
    int bcol;
    if (col0 < split) { Bsel = B0; bcol = col0; }
    else              { Bsel = B1; bcol = col0 - split; }
    if (flags & F_EXPERT) {
        int e = 0;
        #pragma unroll
        for (int i = 1; i < E_NUM; i++) if (row0 >= d_poff[i]) e = i;
        Bsel += (long long)e * ew_stride;
    }
    const float* Bp = Bsel + bcol;

    int t = threadIdx.x;
    if (t < BM) {
        int gr = row0 + t;
        s_map[t] = (flags & (F_GATHER | F_SCATTER)) ? d_perm[gr] : gr;
    }
    __syncthreads();

    float acc[8][8];
    #pragma unroll
    for (int i = 0; i < 8; i++)
        #pragma unroll
        for (int j = 0; j < 8; j++) acc[i][j] = 0.f;

    int ty = t >> 4, tx = t & 15;   // 16x16 thread grid

    for (int kt = 0; kt < K; kt += BK) {
        // A tile: 128 rows x 16 k; 512 float4 loads, 2 per thread; store transposed
        #pragma unroll
        for (int q2 = 0; q2 < 2; q2++) {
            int q  = t * 2 + q2;
            int r  = q >> 2;            // 0..127
            int kq = (q & 3) * 4;       // 0,4,8,12
            int arow = (flags & F_GATHER) ? s_map[r] : (row0 + r);
            float4 v = make_float4(0.f, 0.f, 0.f, 0.f);
            if (arow >= 0)
                v = *reinterpret_cast<const float4*>(&A[(long long)arow * K + kt + kq]);
            As[kq + 0][r] = v.x; As[kq + 1][r] = v.y;
            As[kq + 2][r] = v.z; As[kq + 3][r] = v.w;
        }
        // B tile: 16 k x 128 cols; 512 float4 loads, 2 per thread
        #pragma unroll
        for (int q2 = 0; q2 < 2; q2++) {
            int q  = t * 2 + q2;
            int kk = q >> 5;            // 0..15
            int n4 = (q & 31) * 4;
            float4 v = *reinterpret_cast<const float4*>(&Bp[(long long)(kt + kk) * ldb + n4]);
            *reinterpret_cast<float4*>(&Bs[kk][n4]) = v;
        }
        __syncthreads();

        #pragma unroll
        for (int kk = 0; kk < BK; kk++) {
            float a[8], b[8];
            #pragma unroll
            for (int i = 0; i < 8; i++) a[i] = As[kk][ty * 8 + i];
            #pragma unroll
            for (int j = 0; j < 8; j++) b[j] = Bs[kk][tx * 8 + j];
            #pragma unroll
            for (int i = 0; i < 8; i++)
                #pragma unroll
                for (int j = 0; j < 8; j++)
                    acc[i][j] += a[i] * b[j];
        }
        __syncthreads();
    }

    // epilogue
    #pragma unroll
    for (int i = 0; i < 8; i++) {
        int r = ty * 8 + i;
        int crow = (flags & F_SCATTER) ? s_map[r] : (row0 + r);
        if (crow < 0) continue;
        float* Cr = &C[(long long)crow * ldc + col0 + tx * 8];
        if (flags & F_ACCUM) {
            #pragma unroll
            for (int j = 0; j < 8; j++) Cr[j] += acc[i][j];
        } else {
            *reinterpret_cast<float4*>(&Cr[0]) = make_float4(acc[i][0], acc[i][1], acc[i][2], acc[i][3]);
            *reinterpret_cast<float4*>(&Cr[4]) = make_float4(acc[i][4], acc[i][5], acc[i][6], acc[i][7]);
        }
    }
}

// ---------------- SwiGLU elementwise ----------------------------------------
__device__ __forceinline__ float silu_f(float g) {
    return g / (1.f + __expf(-g));
}

__global__ void k_swiglu_shared() {
    long long idx = (long long)blockIdx.x * blockDim.x + threadIdx.x;  // N_TOK*1024 exact grid
    long long r = idx >> 10;
    int c = (int)(idx & 1023);
    float g = g_GUs[r * 2048 + c];
    float u = g_GUs[r * 2048 + 1024 + c];
    g_Hs[idx] = u * silu_f(g);
}

__global__ void k_swiglu_routed() {
    long long idx = (long long)blockIdx.x * blockDim.x + threadIdx.x;  // PADMAX*512 exact grid
    int r = (int)(idx >> 9);
    int c = (int)(idx & 511);
    if (r < d_padded_total) {
        float g = g_GUr[(long long)r * 1024 + c];
        float u = g_GUr[(long long)r * 1024 + 512 + c];
        g_Hr[idx] = u * silu_f(g);
    }
}

// ---------------- launch ----------------------------------------------------
extern "C" void kernel_launch(void* const* d_in, const int* in_sizes, int n_in,
                              void* d_out, int out_size) {
    const float* x      = (const float*)d_in[0];  // [N,1024]
    const int*   tok    = (const int*)  d_in[1];  // [N]
    const float* gate_w = (const float*)d_in[2];  // [8,1024,512]
    const float* up_w   = (const float*)d_in[3];  // [8,1024,512]
    const float* down_w = (const float*)d_in[4];  // [8,512,1024]
    const float* sg     = (const float*)d_in[5];  // [1024,1024]
    const float* su     = (const float*)d_in[6];  // [1024,1024]
    const float* sd     = (const float*)d_in[7];  // [1024,1024]
    float* out = (float*)d_out;                   // [N,1024]

    float *GUs, *Hs, *GUr, *Hr;
    cudaGetSymbolAddress((void**)&GUs, g_GUs);
    cudaGetSymbolAddress((void**)&Hs,  g_Hs);
    cudaGetSymbolAddress((void**)&GUr, g_GUr);
    cudaGetSymbolAddress((void**)&Hr,  g_Hr);

    // routing: group tokens by expert into 128-padded groups
    k_init   <<<(PADMAX + 255) / 256, 256>>>();
    k_hist   <<<(N_TOK + 255) / 256, 256>>>(tok);
    k_scan   <<<1, 32>>>();
    k_scatter<<<(N_TOK + 255) / 256, 256>>>(tok);

    // shared up-proj: GUs[N,2048] = x @ [sg | su]
    k_sgemm<<<dim3(2048 / BN, N_TOK / BM), 256>>>(
        x, sg, su, GUs, /*K*/H_DIM, /*split*/1024, /*ldb*/1024, /*ldc*/2048,
        0LL, 0);

    // routed up-proj: GUr[pad,1024] = gather(x) @ [gate_w[e] | up_w[e]]
    k_sgemm<<<dim3(1024 / BN, PADMAX / BM), 256>>>(
        x, gate_w, up_w, GUr, /*K*/H_DIM, /*split*/512, /*ldb*/512, /*ldc*/1024,
        (long long)H_DIM * E_DIM, F_GATHER | F_EXPERT | F_LIMIT);

    // activations
    k_swiglu_shared<<<(unsigned)((long long)N_TOK * 1024 / 256), 256>>>();
    k_swiglu_routed<<<(unsigned)((long long)PADMAX * 512 / 256), 256>>>();

    // shared down-proj: out = Hs @ sd   (full overwrite of poisoned d_out)
    k_sgemm<<<dim3(1024 / BN, N_TOK / BM), 256>>>(
        Hs, sd, sd, out, /*K*/H_DIM, /*split*/1 << 28, /*ldb*/1024, /*ldc*/1024,
        0LL, 0);

    // routed down-proj: out[perm[r]] += Hr[r] @ down_w[e]   (after shared pass)
    k_sgemm<<<dim3(1024 / BN, PADMAX / BM), 256>>>(
        Hr, down_w, down_w, out, /*K*/E_DIM, /*split*/1 << 28, /*ldb*/1024, /*ldc*/1024,
        (long long)E_DIM * H_DIM, F_SCATTER | F_ACCUM | F_EXPERT | F_LIMIT);
}

// round 5
// speedup vs baseline: 3.8722x; 3.8722x over previous
#include <cuda_runtime.h>
#include <cstdint>
#include <math.h>

// ---------------- problem constants -----------------------------------------
#define N_TOK 16384
#define H_DIM 1024
#define E_NUM 8
#define E_DIM 512
#define VOCAB 50257
#define PADMAX (N_TOK + E_NUM * 128)   // 17408

// ---------------- device state & scratch -------------------------------------
__device__ int d_counts[E_NUM];
__device__ int d_cursor[E_NUM];
__device__ int d_poff[E_NUM + 1];
__device__ int d_padded_total;
__device__ int d_perm[PADMAX];
__device__ int d_inv[N_TOK];

__device__ float g_Xs [(size_t)N_TOK * 1024];    // tf32-rounded x
__device__ float g_Xg [(size_t)PADMAX * 1024];   // gathered+rounded x
__device__ float g_GUs[(size_t)N_TOK * 2048];    // shared gate|up
__device__ float g_Hs [(size_t)N_TOK * 1024];
__device__ float g_GUr[(size_t)PADMAX * 1024];   // routed gate|up
__device__ float g_Hr [(size_t)PADMAX * 512];
__device__ float g_Or [(size_t)PADMAX * 1024];
__device__ float g_sgT[(size_t)1024 * 1024];
__device__ float g_suT[(size_t)1024 * 1024];
__device__ float g_sdT[(size_t)1024 * 1024];
__device__ float g_gT [(size_t)E_NUM * 512 * 1024];
__device__ float g_uT [(size_t)E_NUM * 512 * 1024];
__device__ float g_dT [(size_t)E_NUM * 1024 * 512];

// ---------------- helpers -----------------------------------------------------
__device__ __forceinline__ float tf32r(float x) {
    uint32_t u;
    asm("cvt.rna.tf32.f32 %0, %1;" : "=r"(u) : "f"(x));
    return __uint_as_float(u);
}
__device__ __forceinline__ uint32_t smem_u32(const void* p) {
    uint32_t a;
    asm("{ .reg .u64 t; cvta.to.shared.u64 t, %1; cvt.u32.u64 %0, t; }" : "=r"(a) : "l"(p));
    return a;
}
#define CP_ASYNC16(dst, src) \
    asm volatile("cp.async.cg.shared.global [%0], [%1], 16;" :: "r"(dst), "l"(src))
#define CP_COMMIT() asm volatile("cp.async.commit_group;")
#define CP_WAIT1()  asm volatile("cp.async.wait_group 1;")

#define LDSM4(r, addr) \
    asm volatile("ldmatrix.sync.aligned.m8n8.x4.shared.b16 {%0,%1,%2,%3}, [%4];" \
        : "=r"((r)[0]), "=r"((r)[1]), "=r"((r)[2]), "=r"((r)[3]) : "r"(addr))

__device__ __forceinline__ void mma8(float* d, const uint32_t* a, uint32_t b0, uint32_t b1) {
    asm volatile("mma.sync.aligned.m16n8k8.row.col.f32.tf32.tf32.f32 "
        "{%0,%1,%2,%3}, {%4,%5,%6,%7}, {%8,%9}, {%0,%1,%2,%3};"
        : "+f"(d[0]), "+f"(d[1]), "+f"(d[2]), "+f"(d[3])
        : "r"(a[0]), "r"(a[1]), "r"(a[2]), "r"(a[3]), "r"(b0), "r"(b1));
}

// ---------------- routing -----------------------------------------------------
__global__ void k_init() {
    int i = blockIdx.x * blockDim.x + threadIdx.x;
    if (i < E_NUM) { d_counts[i] = 0; d_cursor[i] = 0; }
    for (int j = i; j < PADMAX; j += gridDim.x * blockDim.x) d_perm[j] = -1;
}
__device__ __forceinline__ int expert_of(int t) {
    t = t < 0 ? 0 : (t > VOCAB - 1 ? VOCAB - 1 : t);
    return t & (E_NUM - 1);
}
__global__ void k_hist(const int* __restrict__ tok) {
    int i = blockIdx.x * blockDim.x + threadIdx.x;
    if (i < N_TOK) atomicAdd(&d_counts[expert_of(tok[i])], 1);
}
__global__ void k_scan() {
    if (threadIdx.x == 0) {
        int acc = 0; d_poff[0] = 0;
        for (int e = 0; e < E_NUM; e++) { acc += (d_counts[e] + 127) & ~127; d_poff[e + 1] = acc; }
        d_padded_total = acc;
    }
}
__global__ void k_scatter(const int* __restrict__ tok) {
    int i = blockIdx.x * blockDim.x + threadIdx.x;
    if (i < N_TOK) {
        int e = expert_of(tok[i]);
        int p = atomicAdd(&d_cursor[e], 1);
        int r = d_poff[e] + p;
        d_perm[r] = i;
        d_inv[i] = r;
    }
}

// ---------------- aux kernels -------------------------------------------------
__global__ void k_transpose(const float* __restrict__ in, float* __restrict__ out, int R, int C) {
    __shared__ float tile[32][33];
    int b = blockIdx.z;
    int r0 = blockIdx.y * 32, c0 = blockIdx.x * 32;
    const float* ip = in + (size_t)b * R * C;
    float* op = out + (size_t)b * R * C;
    int tx = threadIdx.x, ty = threadIdx.y;
    #pragma unroll
    for (int i = 0; i < 32; i += 8) tile[ty + i][tx] = ip[(size_t)(r0 + ty + i) * C + c0 + tx];
    __syncthreads();
    #pragma unroll
    for (int i = 0; i < 32; i += 8) op[(size_t)(c0 + ty + i) * R + r0 + tx] = tf32r(tile[tx][ty + i]);
}

__global__ void k_round(const float* __restrict__ in, float* __restrict__ out) {
    size_t i = (size_t)blockIdx.x * blockDim.x + threadIdx.x;   // N_TOK*256 float4
    float4 v = reinterpret_cast<const float4*>(in)[i];
    reinterpret_cast<float4*>(out)[i] =
        make_float4(tf32r(v.x), tf32r(v.y), tf32r(v.z), tf32r(v.w));
}

__global__ void k_gather(const float* __restrict__ x) {
    int i = blockIdx.x * blockDim.x + threadIdx.x;   // PADMAX*256 float4
    int r = i >> 8, c4 = i & 255;
    int src = d_perm[r];
    float4 v = make_float4(0.f, 0.f, 0.f, 0.f);
    if (src >= 0) {
        v = reinterpret_cast<const float4*>(x)[(size_t)src * 256 + c4];
        v = make_float4(tf32r(v.x), tf32r(v.y), tf32r(v.z), tf32r(v.w));
    }
    reinterpret_cast<float4*>(g_Xg)[(size_t)r * 256 + c4] = v;
}

__device__ __forceinline__ float silu_f(float g) { return g / (1.f + __expf(-g)); }

__global__ void k_swiglu_s() {
    size_t i = (size_t)blockIdx.x * blockDim.x + threadIdx.x;   // N_TOK*256
    size_t r = i >> 8; int c4 = (int)(i & 255);
    float4 g = reinterpret_cast<const float4*>(g_GUs)[r * 512 + c4];
    float4 u = reinterpret_cast<const float4*>(g_GUs)[r * 512 + 256 + c4];
    reinterpret_cast<float4*>(g_Hs)[i] = make_float4(
        tf32r(silu_f(g.x) * u.x), tf32r(silu_f(g.y) * u.y),
        tf32r(silu_f(g.z) * u.z), tf32r(silu_f(g.w) * u.w));
}
__global__ void k_swiglu_r() {
    size_t i = (size_t)blockIdx.x * blockDim.x + threadIdx.x;   // PADMAX*128
    size_t r = i >> 7; int c4 = (int)(i & 127);
    float4 g = reinterpret_cast<const float4*>(g_GUr)[r * 256 + c4];
    float4 u = reinterpret_cast<const float4*>(g_GUr)[r * 256 + 128 + c4];
    reinterpret_cast<float4*>(g_Hr)[i] = make_float4(
        tf32r(silu_f(g.x) * u.x), tf32r(silu_f(g.y) * u.y),
        tf32r(silu_f(g.z) * u.z), tf32r(silu_f(g.w) * u.w));
}
__global__ void k_combine(float* __restrict__ out) {
    int i = blockIdx.x * blockDim.x + threadIdx.x;   // N_TOK*256
    int t = i >> 8, c4 = i & 255;
    float4 a = reinterpret_cast<const float4*>(out)[i];
    float4 b = reinterpret_cast<const float4*>(g_Or)[(size_t)d_inv[t] * 256 + c4];
    reinterpret_cast<float4*>(out)[i] = make_float4(a.x + b.x, a.y + b.y, a.z + b.z, a.w + b.w);
}

// ---------------- tf32 mma.sync GEMM -----------------------------------------
// C[M,N] = A[M,K] @ Bt[N,K]^T.  BM=BN=128, BK=32, 3-stage cp.async, 256 thr.
#define BKG 32
#define RS 36                       // smem row stride (floats), 144B (16B mult)
#define STG_F (128 * RS)            // floats per tile per stage
#define STG_B (STG_F * 4)
#define NST 3
#define GEMM_SMEM (NST * STG_B * 2)
#define F_EXPERT 1
#define F_LIMIT  2

__global__ __launch_bounds__(256)
void k_mma(const float* __restrict__ A, const float* __restrict__ B0,
           const float* __restrict__ B1, float* __restrict__ C,
           int K, int split, long long ew_stride, int ldc, int flags)
{
    extern __shared__ __align__(128) float sm[];
    int row0 = blockIdx.y * 128;
    if ((flags & F_LIMIT) && row0 >= d_padded_total) return;
    int col0 = blockIdx.x * 128;

    const float* Bsel; int bcol;
    if (col0 < split) { Bsel = B0; bcol = col0; }
    else              { Bsel = B1; bcol = col0 - split; }
    if (flags & F_EXPERT) {
        int e = 0;
        #pragma unroll
        for (int i = 1; i < E_NUM; i++) if (row0 >= d_poff[i]) e = i;
        Bsel += (long long)e * ew_stride;
    }
    const float* Ap = A + (size_t)row0 * K;
    const float* Bp = Bsel + (size_t)bcol * K;

    int tid = threadIdx.x;
    uint32_t sA = smem_u32(sm);
    uint32_t sB = sA + NST * STG_B;

    int lane = tid & 31, wid = tid >> 5;
    int wm = wid >> 1, wn = wid & 1;            // 4 x 2 warps
    int tq = lane & 7, sel = lane >> 3;

    // ldmatrix per-thread byte offsets within a stage
    uint32_t aoff[2], boff[4];
    #pragma unroll
    for (int fm = 0; fm < 2; fm++)
        aoff[fm] = (uint32_t)((wm * 32 + fm * 16 + tq + (sel & 1) * 8) * 144 + ((sel >> 1) * 4) * 4);
    #pragma unroll
    for (int p = 0; p < 4; p++)
        boff[p] = (uint32_t)((wn * 64 + p * 16 + tq + (sel >> 1) * 8) * 144 + ((sel & 1) * 4) * 4);

    // cp.async loader: 1024 16B chunks per tile, 4 per thread
    auto load_stage = [&](int st, int kt) {
        uint32_t da = sA + st * STG_B, db = sB + st * STG_B;
        const float* ga = Ap + kt * BKG;
        const float* gb = Bp + kt * BKG;
        #pragma unroll
        for (int p = 0; p < 4; p++) {
            int g = p * 256 + tid;
            int r = g >> 3, c = g & 7;
            CP_ASYNC16(da + (uint32_t)(r * 144 + c * 16), ga + (size_t)r * K + c * 4);
            CP_ASYNC16(db + (uint32_t)(r * 144 + c * 16), gb + (size_t)r * K + c * 4);
        }
    };

    int KT = K / BKG;
    load_stage(0, 0); CP_COMMIT();
    load_stage(1, 1); CP_COMMIT();
    CP_WAIT1();
    __syncthreads();

    float acc[2][8][4];
    #pragma unroll
    for (int fm = 0; fm < 2; fm++)
        #pragma unroll
        for (int fn = 0; fn < 8; fn++)
            #pragma unroll
            for (int q = 0; q < 4; q++) acc[fm][fn][q] = 0.f;

    for (int kt = 0; kt < KT; kt++) {
        int st = kt % NST;
        uint32_t baseA = sA + st * STG_B, baseB = sB + st * STG_B;
        #pragma unroll
        for (int s = 0; s < 4; s++) {
            uint32_t a[2][4], b[4][4];
            #pragma unroll
            for (int fm = 0; fm < 2; fm++) LDSM4(a[fm], baseA + aoff[fm] + s * 32);
            #pragma unroll
            for (int p = 0; p < 4; p++)  LDSM4(b[p], baseB + boff[p] + s * 32);
            #pragma unroll
            for (int fm = 0; fm < 2; fm++)
                #pragma unroll
                for (int fn = 0; fn < 8; fn++) {
                    const uint32_t* bp = b[fn >> 1];
                    if (fn & 1) mma8(acc[fm][fn], a[fm], bp[2], bp[3]);
                    else        mma8(acc[fm][fn], a[fm], bp[0], bp[1]);
                }
        }
        if (kt + 2 < KT) load_stage((kt + 2) % NST, kt + 2);
        CP_COMMIT();
        CP_WAIT1();
        __syncthreads();
    }

    // epilogue
    int gid = lane >> 2, tig = lane & 3;
    #pragma unroll
    for (int fm = 0; fm < 2; fm++) {
        #pragma unroll
        for (int fn = 0; fn < 8; fn++) {
            int r = row0 + wm * 32 + fm * 16 + gid;
            int c = col0 + wn * 64 + fn * 8 + 2 * tig;
            float2 v0 = make_float2(acc[fm][fn][0], acc[fm][fn][1]);
            float2 v1 = make_float2(acc[fm][fn][2], acc[fm][fn][3]);
            *reinterpret_cast<float2*>(&C[(size_t)r * ldc + c]) = v0;
            *reinterpret_cast<float2*>(&C[(size_t)(r + 8) * ldc + c]) = v1;
        }
    }
}

// ---------------- launch ------------------------------------------------------
extern "C" void kernel_launch(void* const* d_in, const int* in_sizes, int n_in,
                              void* d_out, int out_size) {
    const float* x      = (const float*)d_in[0];
    const int*   tok    = (const int*)  d_in[1];
    const float* gate_w = (const float*)d_in[2];
    const float* up_w   = (const float*)d_in[3];
    const float* down_w = (const float*)d_in[4];
    const float* sg     = (const float*)d_in[5];
    const float* su     = (const float*)d_in[6];
    const float* sd     = (const float*)d_in[7];
    float* out = (float*)d_out;

    float *Xs, *Xg, *GUs, *Hs, *GUr, *Hr, *Or, *sgT, *suT, *sdT, *gT, *uT, *dT;
    cudaGetSymbolAddress((void**)&Xs, g_Xs);   cudaGetSymbolAddress((void**)&Xg, g_Xg);
    cudaGetSymbolAddress((void**)&GUs, g_GUs); cudaGetSymbolAddress((void**)&Hs, g_Hs);
    cudaGetSymbolAddress((void**)&GUr, g_GUr); cudaGetSymbolAddress((void**)&Hr, g_Hr);
    cudaGetSymbolAddress((void**)&Or, g_Or);
    cudaGetSymbolAddress((void**)&sgT, g_sgT); cudaGetSymbolAddress((void**)&suT, g_suT);
    cudaGetSymbolAddress((void**)&sdT, g_sdT); cudaGetSymbolAddress((void**)&gT, g_gT);
    cudaGetSymbolAddress((void**)&uT, g_uT);   cudaGetSymbolAddress((void**)&dT, g_dT);

    cudaFuncSetAttribute(k_mma, cudaFuncAttributeMaxDynamicSharedMemorySize, GEMM_SMEM);

    // routing
    k_init   <<<(PADMAX + 255) / 256, 256>>>();
    k_hist   <<<(N_TOK + 255) / 256, 256>>>(tok);
    k_scan   <<<1, 32>>>();
    k_scatter<<<(N_TOK + 255) / 256, 256>>>(tok);

    // weight transposes ([K,N] -> [N,K]) with tf32 rounding
    dim3 tb(32, 8);
    k_transpose<<<dim3(32, 32, 1), tb>>>(sg, sgT, 1024, 1024);
    k_transpose<<<dim3(32, 32, 1), tb>>>(su, suT, 1024, 1024);
    k_transpose<<<dim3(32, 32, 1), tb>>>(sd, sdT, 1024, 1024);
    k_transpose<<<dim3(16, 32, E_NUM), tb>>>(gate_w, gT, 1024, 512);
    k_transpose<<<dim3(16, 32, E_NUM), tb>>>(up_w,   uT, 1024, 512);
    k_transpose<<<dim3(32, 16, E_NUM), tb>>>(down_w, dT, 512, 1024);

    // activation prep
    k_round <<<N_TOK, 256>>>(x, Xs);
    k_gather<<<PADMAX, 256>>>(x);

    // shared up: GUs[N,2048] = Xs @ [sgT|suT]^T
    k_mma<<<dim3(16, 128), 256, GEMM_SMEM>>>(Xs, sgT, suT, GUs, 1024, 1024, 0LL, 2048, 0);
    k_swiglu_s<<<N_TOK, 256>>>();

    // routed up: GUr[pad,1024] = Xg @ [gT[e]|uT[e]]^T
    k_mma<<<dim3(8, PADMAX / 128), 256, GEMM_SMEM>>>(Xg, gT, uT, GUr, 1024, 512,
        (long long)512 * 1024, 1024, F_EXPERT | F_LIMIT);
    k_swiglu_r<<<PADMAX / 2, 256>>>();

    // shared down: out = Hs @ sdT^T
    k_mma<<<dim3(8, 128), 256, GEMM_SMEM>>>(Hs, sdT, sdT, out, 1024, 1 << 28, 0LL, 1024, 0);

    // routed down: Or = Hr @ dT[e]^T
    k_mma<<<dim3(8, PADMAX / 128), 256, GEMM_SMEM>>>(Hr, dT, dT, Or, 512, 1 << 28,
        (long long)1024 * 512, 1024, F_EXPERT | F_LIMIT);

    // combine
    k_combine<<<N_TOK, 256>>>(out);
}